// round 13
// baseline (speedup 1.0000x reference)
#include <cuda_runtime.h>
#include <math.h>

#define B_DIM 64
#define C_DIM 80
#define T_DIM 16384
#define NTHREADS 256
#define NWARPS 8
#define CAP 4096
#define HBIN 256
#define NHIST (3 * HBIN)
#define BINBUF 32
#define FULL 0xFFFFFFFFu

// fixed brackets around N(0,1) quartiles; exactness never depends on these
#define LO0 (-0.7544898f)
#define HI0 (-0.5944898f)
#define LO1 (-0.08f)
#define HI1 (0.08f)
#define LO2 (0.5944898f)
#define HI2 (0.7544898f)
#define HSCALE (256.0f / 0.16f)   // mini-hist bins per bracket width

// order-preserving float <-> u32 key (exact total order incl. ties/-0)
__device__ __forceinline__ unsigned f2k(float f) {
    unsigned u = __float_as_uint(f);
    return u ^ ((unsigned)((int)u >> 31) | 0x80000000u);
}
__device__ __forceinline__ float k2f(unsigned k) {
    unsigned m = (k & 0x80000000u) ? 0x80000000u : 0xFFFFFFFFu;
    return __uint_as_float(k ^ m);
}

__device__ __forceinline__ float bracket_lo(int q) {
    return q == 0 ? LO0 : (q == 1 ? LO1 : LO2);
}

__global__ void __launch_bounds__(NTHREADS, 8)
statpool_kernel(const float* __restrict__ x, const int* __restrict__ lengths,
                float* __restrict__ out) {
    __shared__ float list[CAP];          // merged in-bracket candidates
    __shared__ unsigned hist[NHIST];     // 3 brackets x 256 bins -> cumsum
    __shared__ float red_s[NWARPS], red_s2[NWARPS];
    __shared__ unsigned wtot[NWARPS], wbase[NWARPS];
    __shared__ int s_k[6];
    __shared__ float s_w[3];
    __shared__ int s_below[3];           // exact count of f < lo_q
    __shared__ int s_cnt;
    __shared__ int s_tbin[6], s_kib[6], s_m[6], s_ok[6];
    __shared__ unsigned binbuf[6 * BINBUF];
    __shared__ int bcnt[6];
    __shared__ unsigned s_keyout[6];

    const int row = blockIdx.x;
    const int b = row / C_DIM, c = row % C_DIM;
    const int n = lengths[b];
    const int tid = threadIdx.x, lane = tid & 31, warp = tid >> 5;

    for (int i = tid; i < NHIST; i += NTHREADS) hist[i] = 0u;
    if (tid < 6) bcnt[tid] = 0;
    if (tid < 3) s_below[tid] = 0;
    if (tid == 0) s_cnt = 0;
    __syncthreads();

    // ---- SINGLE fused pass: sum/sumsq + below-counts + bracket compaction.
    //      Pivots are immediates; no dependency on any prior pass. ----
    const float* xrow = x + (size_t)row * T_DIM;
    const float4* x4 = (const float4*)xrow;
    const int nfull = n >> 2;
    float sum = 0.f, sumsq = 0.f;
    int c0 = 0, c1 = 0, c2 = 0;
    for (int i = tid; i < nfull; i += NTHREADS) {
        float4 v = x4[i];
        sum += v.x + v.y + v.z + v.w;
        sumsq = fmaf(v.x, v.x, sumsq); sumsq = fmaf(v.y, v.y, sumsq);
        sumsq = fmaf(v.z, v.z, sumsq); sumsq = fmaf(v.w, v.w, sumsq);
        bool i0, i1, i2, i3;
        {
            int a = (v.x < LO0) + (v.x < LO1) + (v.x < LO2);
            int h = (v.x < HI0) + (v.x < HI1) + (v.x < HI2);
            c0 += (v.x < LO0); c1 += (v.x < LO1); c2 += (v.x < LO2);
            i0 = (a != h);
        }
        {
            int a = (v.y < LO0) + (v.y < LO1) + (v.y < LO2);
            int h = (v.y < HI0) + (v.y < HI1) + (v.y < HI2);
            c0 += (v.y < LO0); c1 += (v.y < LO1); c2 += (v.y < LO2);
            i1 = (a != h);
        }
        {
            int a = (v.z < LO0) + (v.z < LO1) + (v.z < LO2);
            int h = (v.z < HI0) + (v.z < HI1) + (v.z < HI2);
            c0 += (v.z < LO0); c1 += (v.z < LO1); c2 += (v.z < LO2);
            i2 = (a != h);
        }
        {
            int a = (v.w < LO0) + (v.w < LO1) + (v.w < LO2);
            int h = (v.w < HI0) + (v.w < HI1) + (v.w < HI2);
            c0 += (v.w < LO0); c1 += (v.w < LO1); c2 += (v.w < LO2);
            i3 = (a != h);
        }
        int hh = (int)i0 + (int)i1 + (int)i2 + (int)i3;
        if (hh) {                        // one atomic covers up to 4 appends
            int p = atomicAdd(&s_cnt, hh);
            if (i0) { if (p < CAP) list[p] = v.x; p++; }
            if (i1) { if (p < CAP) list[p] = v.y; p++; }
            if (i2) { if (p < CAP) list[p] = v.z; p++; }
            if (i3) { if (p < CAP) list[p] = v.w; p++; }
        }
    }
    if (tid == 0) {                      // tail: <=3 elements
        for (int t = nfull << 2; t < n; ++t) {
            float f = xrow[t];
            sum += f; sumsq = fmaf(f, f, sumsq);
            int a = (f < LO0) + (f < LO1) + (f < LO2);
            int h = (f < HI0) + (f < HI1) + (f < HI2);
            c0 += (f < LO0); c1 += (f < LO1); c2 += (f < LO2);
            if (a != h) { int p = atomicAdd(&s_cnt, 1); if (p < CAP) list[p] = f; }
        }
    }

    // ---- block reductions (uniform control flow) ----
#pragma unroll
    for (int o = 16; o; o >>= 1) {
        sum += __shfl_down_sync(FULL, sum, o);
        sumsq += __shfl_down_sync(FULL, sumsq, o);
        c0 += __shfl_down_sync(FULL, c0, o);
        c1 += __shfl_down_sync(FULL, c1, o);
        c2 += __shfl_down_sync(FULL, c2, o);
    }
    if (lane == 0) {
        red_s[warp] = sum; red_s2[warp] = sumsq;
        atomicAdd(&s_below[0], c0);
        atomicAdd(&s_below[1], c1);
        atomicAdd(&s_below[2], c2);
    }
    __syncthreads();

    if (tid == 0) {
        float s = 0.f, s2 = 0.f;
#pragma unroll
        for (int w = 0; w < NWARPS; ++w) { s += red_s[w]; s2 += red_s2[w]; }
        float fn = (float)n;
        float mean = s / fn;
        float var = fmaxf(s2 / fn - mean * mean, 1e-6f);
        out[b * (5 * C_DIM) + 0 * C_DIM + c] = mean;
        out[b * (5 * C_DIM) + 1 * C_DIM + c] = sqrtf(var);
        float n1 = (float)(n - 1);
        const float qs[3] = {0.25f, 0.5f, 0.75f};
#pragma unroll
        for (int q = 0; q < 3; ++q) {
            float pos = qs[q] * n1;
            float flo = floorf(pos);
            s_k[2 * q]     = (int)flo;
            s_k[2 * q + 1] = (int)ceilf(pos);
            s_w[q] = pos - flo;
        }
    }
    __syncthreads();

    const int cnt = min(s_cnt, CAP);
    const int ovf = (s_cnt > CAP);

    // ---- phase 3a: mini-histogram over candidates only ----
    for (int i = tid; i < cnt; i += NTHREADS) {
        float f = list[i];
        int q = (int)(f >= LO1) + (int)(f >= LO2);   // brackets disjoint
        int bin = (int)((f - bracket_lo(q)) * HSCALE);
        bin = max(0, min(HBIN - 1, bin));
        atomicAdd(&hist[q * HBIN + bin], 1u);
    }
    __syncthreads();

    // ---- phase 3b: inclusive scan of 768 bins (thread owns 3) ----
    unsigned h0 = hist[tid * 3], h1 = hist[tid * 3 + 1], h2 = hist[tid * 3 + 2];
    unsigned loc = h0 + h1 + h2;
    unsigned incv = loc;
#pragma unroll
    for (int o = 1; o < 32; o <<= 1) {
        unsigned t = __shfl_up_sync(FULL, incv, o);
        if (lane >= o) incv += t;
    }
    if (lane == 31) wtot[warp] = incv;
    __syncthreads();
    if (warp == 0) {
        unsigned t = (lane < NWARPS) ? wtot[lane] : 0u;
        unsigned ti = t;
#pragma unroll
        for (int o = 1; o < NWARPS; o <<= 1) {
            unsigned u = __shfl_up_sync(FULL, ti, o);
            if (lane >= o) ti += u;
        }
        if (lane < NWARPS) wbase[lane] = ti - t;
    }
    __syncthreads();
    unsigned run = wbase[warp] + (incv - loc);
    run += h0; hist[tid * 3] = run;
    run += h1; hist[tid * 3 + 1] = run;
    run += h2; hist[tid * 3 + 2] = run;
    __syncthreads();

    // ---- phase 3c: locate bin per target (6 threads) ----
    if (tid < 6) {
        const int q = tid >> 1;
        const int base = q ? (int)hist[q * HBIN - 1] : 0;
        const int total = (int)hist[q * HBIN + HBIN - 1] - base;
        const int krem = s_k[tid] - s_below[q];
        int ok = !ovf && krem >= 0 && krem < total;
        if (ok) {
            const int CU = krem + base;
            int lo = q * HBIN, hi = q * HBIN + HBIN - 1;
            while (lo < hi) {
                int mid = (lo + hi) >> 1;
                if ((int)hist[mid] > CU) hi = mid; else lo = mid + 1;
            }
            int prev = (lo > q * HBIN) ? (int)hist[lo - 1] : base;
            int m = (int)hist[lo] - prev;
            if (m > BINBUF) ok = 0;          // rare tie-pileup -> fallback
            s_tbin[tid] = lo;
            s_kib[tid] = CU - prev;
            s_m[tid] = m;
        }
        s_ok[tid] = ok;
    }
    __syncthreads();

    // ---- phase 3d: selection, warp j resolves target j ----
    if (warp < 6) {
        if (s_ok[warp]) {
            const int tb = s_tbin[warp];
            for (int i = lane; i < cnt; i += 32) {
                float f = list[i];
                int q = (int)(f >= LO1) + (int)(f >= LO2);
                int bin = (int)((f - bracket_lo(q)) * HSCALE);
                bin = max(0, min(HBIN - 1, bin)) + q * HBIN;
                if (bin == tb) {
                    int p = atomicAdd(&bcnt[warp], 1);
                    if (p < BINBUF) binbuf[warp * BINBUF + p] = f2k(f);
                }
            }
            __syncwarp();
            const int m = s_m[warp];
            const int kib = s_kib[warp];
            unsigned e = (lane < m) ? binbuf[warp * BINBUF + lane] : 0xFFFFFFFFu;
            int cl = 0, ce = 0;
            for (int t = 0; t < m; ++t) {
                unsigned o = binbuf[warp * BINBUF + t];   // broadcast read
                cl += (o < e);
                ce += (o == e && t < lane);
            }
            if (lane < m && cl + ce == kib) s_keyout[warp] = e;
        } else {
            // exact fallback: 32-step key bisection over the full global row
            const int kglob = s_k[warp];
            unsigned prefix = 0u;
            for (int bit = 31; bit >= 0; --bit) {
                unsigned cand = prefix | (1u << bit);
                unsigned cc = 0;
                for (int i2 = lane; i2 < T_DIM; i2 += 32)
                    if (i2 < n) cc += (f2k(xrow[i2]) < cand) ? 1u : 0u;
#pragma unroll
                for (int o = 16; o; o >>= 1) cc += __shfl_down_sync(FULL, cc, o);
                cc = __shfl_sync(FULL, cc, 0);
                if (cc <= (unsigned)kglob) prefix = cand;
            }
            if (lane == 0) s_keyout[warp] = prefix;
        }
    }
    __syncthreads();

    // ---- quantile interpolation + writeback ----
    if (tid < 3) {
        float vlo = k2f(s_keyout[2 * tid]);
        float vhi = k2f(s_keyout[2 * tid + 1]);
        out[b * (5 * C_DIM) + (2 + tid) * C_DIM + c] = vlo + s_w[tid] * (vhi - vlo);
    }
}

extern "C" void kernel_launch(void* const* d_in, const int* in_sizes, int n_in,
                              void* d_out, int out_size) {
    const float* x;
    const int* lengths;
    if (in_sizes[0] == B_DIM) {
        lengths = (const int*)d_in[0];
        x = (const float*)d_in[1];
    } else {
        x = (const float*)d_in[0];
        lengths = (const int*)d_in[1];
    }
    float* out = (float*)d_out;

    statpool_kernel<<<B_DIM * C_DIM, NTHREADS>>>(x, lengths, out);
}

// round 14
// speedup vs baseline: 1.0130x; 1.0130x over previous
#include <cuda_runtime.h>
#include <math.h>

#define B_DIM 64
#define C_DIM 80
#define T_DIM 16384
#define NTHREADS 256
#define NWARPS 8
#define CAP 4096
#define HBIN 256
#define NHIST (3 * HBIN)
#define BINBUF 32
#define FULL 0xFFFFFFFFu

// coarse bins: bin = clamp(floor(f*128+512), 0, 1023)  (monotone in f)
// fixed brackets (bin indices) around N(0,1) quartiles z=∓0.6745, 0 (±~0.08):
//   b0: [415,435)  values [-0.7578125, -0.6015625)
//   b1: [501,522)  values [-0.0859375,  0.0781250)
//   b2: [588,608)  values [ 0.5937500,  0.7500000)
// Exactness NEVER depends on these: counts/candidates all come from the same
// deterministic bin function; any miss -> exact global fallback.
#define B0LO 415
#define B0HI 435
#define B1LO 501
#define B1HI 522
#define B2LO 588
#define B2HI 608

// order-preserving float <-> u32 key
__device__ __forceinline__ unsigned f2k(float f) {
    unsigned u = __float_as_uint(f);
    return u ^ ((unsigned)((int)u >> 31) | 0x80000000u);
}
__device__ __forceinline__ float k2f(unsigned k) {
    unsigned m = (k & 0x80000000u) ? 0x80000000u : 0xFFFFFFFFu;
    return __uint_as_float(k ^ m);
}

__device__ __forceinline__ int cbin(float f) {
    float bf = fmaf(f, 128.0f, 512.0f);
    bf = fminf(fmaxf(bf, 0.0f), 1023.0f);
    return (int)bf;
}
// fine bin within bracket q (monotone in f; same formula everywhere)
__device__ __forceinline__ int finebin(float f, int q) {
    float lo = (q == 0) ? -0.7578125f : ((q == 1) ? -0.0859375f : 0.59375f);
    float sc = (q == 1) ? 1560.3809f : 1638.4f;
    int fb = (int)((f - lo) * sc);
    return max(0, min(HBIN - 1, fb));
}

// packed f32x2 helpers
__device__ __forceinline__ unsigned long long pk2(float a, float b) {
    unsigned long long r;
    asm("mov.b64 %0, {%1, %2};" : "=l"(r) : "f"(a), "f"(b));
    return r;
}
__device__ __forceinline__ void upk2(float& a, float& b, unsigned long long v) {
    asm("mov.b64 {%0, %1}, %2;" : "=f"(a), "=f"(b) : "l"(v));
}
__device__ __forceinline__ void add2(unsigned long long& acc, unsigned long long v) {
    asm("add.rn.f32x2 %0, %1, %2;" : "=l"(acc) : "l"(acc), "l"(v));
}
__device__ __forceinline__ void fma2(unsigned long long& acc, unsigned long long v) {
    asm("fma.rn.f32x2 %0, %1, %2, %3;" : "=l"(acc) : "l"(v), "l"(v), "l"(acc));
}

__global__ void __launch_bounds__(NTHREADS, 8)
statpool_kernel(const float* __restrict__ x, const int* __restrict__ lengths,
                float* __restrict__ out) {
    __shared__ unsigned tbl[1024];       // packed per-bin increments + flag
    __shared__ float list[CAP];          // in-bracket candidates
    __shared__ unsigned hist[NHIST];
    __shared__ float red_s[NWARPS], red_s2[NWARPS];
    __shared__ unsigned wtot[NWARPS], wbase[NWARPS];
    __shared__ int s_k[6];
    __shared__ float s_w[3];
    __shared__ int s_below[3];
    __shared__ int s_cnt;
    __shared__ int s_tbin[6], s_kib[6], s_m[6], s_ok[6];
    __shared__ unsigned binbuf[6 * BINBUF];
    __shared__ int bcnt[6];
    __shared__ unsigned s_keyout[6];

    const int row = blockIdx.x;
    const int b = row / C_DIM, c = row % C_DIM;
    const int n = lengths[b];
    const int tid = threadIdx.x, lane = tid & 31, warp = tid >> 5;

    // ---- build decision table + init ----
    for (int i = tid; i < 1024; i += NTHREADS) {
        unsigned t = 0;
        if (i < B0LO) t += 1u;
        if (i < B1LO) t += 0x100u;
        if (i < B2LO) t += 0x10000u;
        bool cand = (i >= B0LO && i < B0HI) || (i >= B1LO && i < B1HI) ||
                    (i >= B2LO && i < B2HI);
        if (cand) t += 0x1000000u;
        tbl[i] = t;
    }
    for (int i = tid; i < NHIST; i += NTHREADS) hist[i] = 0u;
    if (tid < 6) bcnt[tid] = 0;
    if (tid < 3) s_below[tid] = 0;
    if (tid == 0) s_cnt = 0;
    __syncthreads();

    // ---- SINGLE fused pass ----
    const float* xrow = x + (size_t)row * T_DIM;
    const float4* x4 = (const float4*)xrow;
    const int nfull = n >> 2;
    unsigned long long sum2 = 0ull, sumsq2 = 0ull;   // packed (0.f,0.f)
    unsigned cpack = 0u;
    for (int i = tid; i < nfull; i += NTHREADS) {
        float4 v = x4[i];
        unsigned long long p01 = pk2(v.x, v.y), p23 = pk2(v.z, v.w);
        add2(sum2, p01); add2(sum2, p23);
        fma2(sumsq2, p01); fma2(sumsq2, p23);
        unsigned t0 = tbl[cbin(v.x)];
        unsigned t1 = tbl[cbin(v.y)];
        unsigned t2 = tbl[cbin(v.z)];
        unsigned t3 = tbl[cbin(v.w)];
        unsigned tsum = t0 + t1 + t2 + t3;   // byte fields can't carry into b24
        cpack += tsum;
        unsigned h = tsum >> 24;
        if (h) {
            int p = atomicAdd(&s_cnt, (int)h);
            if (t0 >= 0x1000000u) { if (p < CAP) list[p] = v.x; p++; }
            if (t1 >= 0x1000000u) { if (p < CAP) list[p] = v.y; p++; }
            if (t2 >= 0x1000000u) { if (p < CAP) list[p] = v.z; p++; }
            if (t3 >= 0x1000000u) { if (p < CAP) list[p] = v.w; p++; }
        }
    }
    float sum, sumsq;
    {
        float a, bb; upk2(a, bb, sum2); sum = a + bb;
        upk2(a, bb, sumsq2); sumsq = a + bb;
    }
    if (tid == 0) {                      // tail: <=3 elements
        for (int t = nfull << 2; t < n; ++t) {
            float f = xrow[t];
            sum += f; sumsq = fmaf(f, f, sumsq);
            unsigned tt = tbl[cbin(f)];
            cpack += tt;
            if (tt >= 0x1000000u) {
                int p = atomicAdd(&s_cnt, 1);
                if (p < CAP) list[p] = f;
            }
        }
    }
    int c0 = (int)(cpack & 0xFFu);
    int c1 = (int)((cpack >> 8) & 0xFFu);
    int c2 = (int)((cpack >> 16) & 0xFFu);
#pragma unroll
    for (int o = 16; o; o >>= 1) {
        sum += __shfl_down_sync(FULL, sum, o);
        sumsq += __shfl_down_sync(FULL, sumsq, o);
        c0 += __shfl_down_sync(FULL, c0, o);
        c1 += __shfl_down_sync(FULL, c1, o);
        c2 += __shfl_down_sync(FULL, c2, o);
    }
    if (lane == 0) {
        red_s[warp] = sum; red_s2[warp] = sumsq;
        atomicAdd(&s_below[0], c0);
        atomicAdd(&s_below[1], c1);
        atomicAdd(&s_below[2], c2);
    }
    __syncthreads();

    if (tid == 0) {
        float s = 0.f, s2 = 0.f;
#pragma unroll
        for (int w = 0; w < NWARPS; ++w) { s += red_s[w]; s2 += red_s2[w]; }
        float fn = (float)n;
        float mean = s / fn;
        float var = fmaxf(s2 / fn - mean * mean, 1e-6f);
        out[b * (5 * C_DIM) + 0 * C_DIM + c] = mean;
        out[b * (5 * C_DIM) + 1 * C_DIM + c] = sqrtf(var);
        float n1 = (float)(n - 1);
        const float qs[3] = {0.25f, 0.5f, 0.75f};
#pragma unroll
        for (int q = 0; q < 3; ++q) {
            float pos = qs[q] * n1;
            float flo = floorf(pos);
            s_k[2 * q]     = (int)flo;
            s_k[2 * q + 1] = (int)ceilf(pos);
            s_w[q] = pos - flo;
        }
    }
    __syncthreads();

    const int cnt = min(s_cnt, CAP);
    const int ovf = (s_cnt > CAP);

    // ---- phase 3a: mini-histogram over candidates only ----
    for (int i = tid; i < cnt; i += NTHREADS) {
        float f = list[i];
        int bi = cbin(f);
        int q = (int)(bi >= B1LO) + (int)(bi >= B2LO);
        atomicAdd(&hist[q * HBIN + finebin(f, q)], 1u);
    }
    __syncthreads();

    // ---- phase 3b: inclusive scan of 768 bins (thread owns 3) ----
    unsigned h0 = hist[tid * 3], h1 = hist[tid * 3 + 1], h2 = hist[tid * 3 + 2];
    unsigned loc = h0 + h1 + h2;
    unsigned incv = loc;
#pragma unroll
    for (int o = 1; o < 32; o <<= 1) {
        unsigned t = __shfl_up_sync(FULL, incv, o);
        if (lane >= o) incv += t;
    }
    if (lane == 31) wtot[warp] = incv;
    __syncthreads();
    if (warp == 0) {
        unsigned t = (lane < NWARPS) ? wtot[lane] : 0u;
        unsigned ti = t;
#pragma unroll
        for (int o = 1; o < NWARPS; o <<= 1) {
            unsigned u = __shfl_up_sync(FULL, ti, o);
            if (lane >= o) ti += u;
        }
        if (lane < NWARPS) wbase[lane] = ti - t;
    }
    __syncthreads();
    unsigned run = wbase[warp] + (incv - loc);
    run += h0; hist[tid * 3] = run;
    run += h1; hist[tid * 3 + 1] = run;
    run += h2; hist[tid * 3 + 2] = run;
    __syncthreads();

    // ---- phase 3c: locate fine bin per target (6 threads) ----
    if (tid < 6) {
        const int q = tid >> 1;
        const int base = q ? (int)hist[q * HBIN - 1] : 0;
        const int total = (int)hist[q * HBIN + HBIN - 1] - base;
        const int krem = s_k[tid] - s_below[q];
        int ok = !ovf && krem >= 0 && krem < total;
        if (ok) {
            const int CU = krem + base;
            int lo = q * HBIN, hi = q * HBIN + HBIN - 1;
            while (lo < hi) {
                int mid = (lo + hi) >> 1;
                if ((int)hist[mid] > CU) hi = mid; else lo = mid + 1;
            }
            int prev = (lo > q * HBIN) ? (int)hist[lo - 1] : base;
            int m = (int)hist[lo] - prev;
            if (m > BINBUF) ok = 0;
            s_tbin[tid] = lo;
            s_kib[tid] = CU - prev;
            s_m[tid] = m;
        }
        s_ok[tid] = ok;
    }
    __syncthreads();

    // ---- phase 3d: selection, warp j resolves target j ----
    if (warp < 6) {
        if (s_ok[warp]) {
            const int tb = s_tbin[warp];
            for (int i = lane; i < cnt; i += 32) {
                float f = list[i];
                int bi = cbin(f);
                int q = (int)(bi >= B1LO) + (int)(bi >= B2LO);
                if (q * HBIN + finebin(f, q) == tb) {
                    int p = atomicAdd(&bcnt[warp], 1);
                    if (p < BINBUF) binbuf[warp * BINBUF + p] = f2k(f);
                }
            }
            __syncwarp();
            const int m = s_m[warp];
            const int kib = s_kib[warp];
            unsigned e = (lane < m) ? binbuf[warp * BINBUF + lane] : 0xFFFFFFFFu;
            int cl = 0, ce = 0;
            for (int t = 0; t < m; ++t) {
                unsigned o = binbuf[warp * BINBUF + t];
                cl += (o < e);
                ce += (o == e && t < lane);
            }
            if (lane < m && cl + ce == kib) s_keyout[warp] = e;
        } else {
            // exact fallback: 32-step key bisection over the full global row
            const int kglob = s_k[warp];
            unsigned prefix = 0u;
            for (int bit = 31; bit >= 0; --bit) {
                unsigned cand = prefix | (1u << bit);
                unsigned cc = 0;
                for (int i2 = lane; i2 < T_DIM; i2 += 32)
                    if (i2 < n) cc += (f2k(xrow[i2]) < cand) ? 1u : 0u;
#pragma unroll
                for (int o = 16; o; o >>= 1) cc += __shfl_down_sync(FULL, cc, o);
                cc = __shfl_sync(FULL, cc, 0);
                if (cc <= (unsigned)kglob) prefix = cand;
            }
            if (lane == 0) s_keyout[warp] = prefix;
        }
    }
    __syncthreads();

    if (tid < 3) {
        float vlo = k2f(s_keyout[2 * tid]);
        float vhi = k2f(s_keyout[2 * tid + 1]);
        out[b * (5 * C_DIM) + (2 + tid) * C_DIM + c] = vlo + s_w[tid] * (vhi - vlo);
    }
}

extern "C" void kernel_launch(void* const* d_in, const int* in_sizes, int n_in,
                              void* d_out, int out_size) {
    const float* x;
    const int* lengths;
    if (in_sizes[0] == B_DIM) {
        lengths = (const int*)d_in[0];
        x = (const float*)d_in[1];
    } else {
        x = (const float*)d_in[0];
        lengths = (const int*)d_in[1];
    }
    float* out = (float*)d_out;

    statpool_kernel<<<B_DIM * C_DIM, NTHREADS>>>(x, lengths, out);
}

// round 15
// speedup vs baseline: 1.5300x; 1.5103x over previous
#include <cuda_runtime.h>
#include <math.h>

#define B_DIM 64
#define C_DIM 80
#define T_DIM 16384
#define NTHREADS 256
#define NWARPS 8
#define NBIN 4096
#define CAP 1024
#define BINBUF 64
#define FULL 0xFFFFFFFFu

// order-preserving float <-> u32 key (exact total order incl. ties/-0)
__device__ __forceinline__ unsigned f2k(float f) {
    unsigned u = __float_as_uint(f);
    return u ^ ((unsigned)((int)u >> 31) | 0x80000000u);
}
__device__ __forceinline__ float k2f(unsigned k) {
    unsigned m = (k & 0x80000000u) ? 0x80000000u : 0xFFFFFFFFu;
    return __uint_as_float(k ^ m);
}

// value-linear bin: 4096 bins across [-4,4]; clamped; monotone; used EVERYWHERE
__device__ __forceinline__ int cbin(float f) {
    int bi = __float2int_rd(fmaf(f, 512.0f, 2048.0f));
    return max(0, min(NBIN - 1, bi));
}

__global__ void __launch_bounds__(NTHREADS, 8)
statpool_kernel(const float* __restrict__ x, const int* __restrict__ lengths,
                float* __restrict__ out) {
    extern __shared__ unsigned sh[];
    unsigned* hist = sh;                 // [4096] counts -> inclusive cumsum
    float* list = (float*)(sh + NBIN);   // [CAP] merged window candidates

    __shared__ float red_s[NWARPS], red_s2[NWARPS];
    __shared__ unsigned wtot[NWARPS], wbase[NWARPS];
    __shared__ int s_k[6];
    __shared__ float s_w[3];
    __shared__ int s_bin[6], s_krem[6], s_m[6];
    __shared__ float s_wl[3], s_wh[3];   // widened float windows per quantile
    __shared__ int s_cnt;
    __shared__ int bcnt[6];
    __shared__ unsigned binbuf[6 * BINBUF];
    __shared__ unsigned s_keyout[6];

    const int row = blockIdx.x;
    const int b = row / C_DIM, c = row % C_DIM;
    const int n = lengths[b];
    const int tid = threadIdx.x, lane = tid & 31, warp = tid >> 5;

    for (int i = tid; i < NBIN; i += NTHREADS) hist[i] = 0u;
    if (tid < 6) bcnt[tid] = 0;
    if (tid == 0) s_cnt = 0;
    __syncthreads();

    // ---- pass 1: sum/sumsq + 4096-bin histogram (low-conflict ATOMS) ----
    const float* xrow = x + (size_t)row * T_DIM;
    const float4* x4 = (const float4*)xrow;
    const int nfull = n >> 2;
    float sum = 0.f, sumsq = 0.f;
    for (int i = tid; i < nfull; i += NTHREADS) {
        float4 v = x4[i];
        sum += v.x + v.y + v.z + v.w;
        sumsq = fmaf(v.x, v.x, sumsq); sumsq = fmaf(v.y, v.y, sumsq);
        sumsq = fmaf(v.z, v.z, sumsq); sumsq = fmaf(v.w, v.w, sumsq);
        atomicAdd(&hist[cbin(v.x)], 1u);
        atomicAdd(&hist[cbin(v.y)], 1u);
        atomicAdd(&hist[cbin(v.z)], 1u);
        atomicAdd(&hist[cbin(v.w)], 1u);
    }
    if (tid == 0) {                      // tail: <=3 elements
        for (int t = nfull << 2; t < n; ++t) {
            float f = xrow[t];
            sum += f; sumsq = fmaf(f, f, sumsq);
            atomicAdd(&hist[cbin(f)], 1u);
        }
    }
#pragma unroll
    for (int o = 16; o; o >>= 1) {
        sum += __shfl_down_sync(FULL, sum, o);
        sumsq += __shfl_down_sync(FULL, sumsq, o);
    }
    if (lane == 0) { red_s[warp] = sum; red_s2[warp] = sumsq; }
    __syncthreads();

    // ---- inclusive scan of hist (16 bins/thread) ----
    unsigned vb[16], loc = 0;
#pragma unroll
    for (int d = 0; d < 16; ++d) { vb[d] = hist[tid * 16 + d]; loc += vb[d]; }
    unsigned inc = loc;
#pragma unroll
    for (int o = 1; o < 32; o <<= 1) {
        unsigned t = __shfl_up_sync(FULL, inc, o);
        if (lane >= o) inc += t;
    }
    if (lane == 31) wtot[warp] = inc;
    __syncthreads();

    if (warp == 0) {
        unsigned t = (lane < NWARPS) ? wtot[lane] : 0u;
        unsigned ti = t;
#pragma unroll
        for (int o = 1; o < NWARPS; o <<= 1) {
            unsigned u = __shfl_up_sync(FULL, ti, o);
            if (lane >= o) ti += u;
        }
        if (lane < NWARPS) wbase[lane] = ti - t;
    } else if (tid == 32) {
        // mean/std + rank targets (concurrent with warp 0's base scan)
        float s = 0.f, s2 = 0.f;
#pragma unroll
        for (int w = 0; w < NWARPS; ++w) { s += red_s[w]; s2 += red_s2[w]; }
        float fn = (float)n;
        float mean = s / fn;
        float var = fmaxf(s2 / fn - mean * mean, 1e-6f);
        out[b * (5 * C_DIM) + 0 * C_DIM + c] = mean;
        out[b * (5 * C_DIM) + 1 * C_DIM + c] = sqrtf(var);
        float n1 = (float)(n - 1);
        const float qs[3] = {0.25f, 0.5f, 0.75f};
#pragma unroll
        for (int q = 0; q < 3; ++q) {
            float pos = qs[q] * n1;
            float flo = floorf(pos);
            s_k[2 * q]     = (int)flo;
            s_k[2 * q + 1] = (int)ceilf(pos);
            s_w[q] = pos - flo;
        }
    }
    __syncthreads();

    unsigned run = wbase[warp] + (inc - loc);
#pragma unroll
    for (int d = 0; d < 16; ++d) { run += vb[d]; hist[tid * 16 + d] = run; }
    __syncthreads();

    // ---- locate bin per target; exact below-count & bin size from cumsum ----
    if (tid < 6) {
        int k = s_k[tid];
        int lo = 0, hi = NBIN - 1;
        while (lo < hi) {
            int mid = (lo + hi) >> 1;
            if ((int)hist[mid] > k) hi = mid; else lo = mid + 1;
        }
        int below = lo ? (int)hist[lo - 1] : 0;
        s_bin[tid] = lo;
        s_krem[tid] = k - below;
        s_m[tid] = (int)hist[lo] - below;
    }
    __syncthreads();

    // ---- build widened float windows (superset of target bins) ----
    if (tid == 0) {
#pragma unroll
        for (int q = 0; q < 3; ++q) {
            int blo = min(s_bin[2 * q], s_bin[2 * q + 1]) - 1;
            int bhi = max(s_bin[2 * q], s_bin[2 * q + 1]) + 2;
            s_wl[q] = (blo <= 0)     ? -__int_as_float(0x7F800000)  // -inf
                                     : (float)(blo - 2048) * (1.0f / 512.0f);
            s_wh[q] = (bhi >= NBIN)  ?  __int_as_float(0x7F800000)  // +inf
                                     : (float)(bhi - 2048) * (1.0f / 512.0f);
        }
    }
    __syncthreads();

    const float wl0 = s_wl[0], wh0 = s_wh[0];
    const float wl1 = s_wl[1], wh1 = s_wh[1];
    const float wl2 = s_wl[2], wh2 = s_wh[2];

    // ---- pass 2: float-window candidacy only (fma pipe); ~40 appends/block ----
    for (int i = tid; i < nfull; i += NTHREADS) {
        float4 v = x4[i];
        float vv[4] = {v.x, v.y, v.z, v.w};
#pragma unroll
        for (int j = 0; j < 4; ++j) {
            float f = vv[j];
            bool cand = ((f >= wl0) & (f < wh0)) | ((f >= wl1) & (f < wh1)) |
                        ((f >= wl2) & (f < wh2));
            if (cand) {
                int p = atomicAdd(&s_cnt, 1);
                if (p < CAP) list[p] = f;
            }
        }
    }
    if (tid == 0) {                      // tail
        for (int t = nfull << 2; t < n; ++t) {
            float f = xrow[t];
            bool cand = ((f >= wl0) & (f < wh0)) | ((f >= wl1) & (f < wh1)) |
                        ((f >= wl2) & (f < wh2));
            if (cand) {
                int p = atomicAdd(&s_cnt, 1);
                if (p < CAP) list[p] = f;
            }
        }
    }
    __syncthreads();

    const int cnt = min(s_cnt, CAP);
    const int ovf = (s_cnt > CAP);

    // ---- selection: warp j resolves target j ----
    if (warp < 6) {
        const int B = s_bin[warp];
        const int mexp = s_m[warp];
        const int krem = s_krem[warp];
        bool need_fb = ovf || (mexp > BINBUF) || (krem < 0) || (krem >= mexp);

        if (!need_fb) {
            // collect exact members of bin B from candidate list
            for (int i = lane; i < cnt; i += 32) {
                float f = list[i];
                if (cbin(f) == B) {
                    int p = atomicAdd(&bcnt[warp], 1);
                    if (p < BINBUF) binbuf[warp * BINBUF + p] = f2k(f);
                }
            }
            __syncwarp();
            if (bcnt[warp] != mexp) need_fb = true;   // verification gate
        }

        if (!need_fb) {
            // exact stable-rank among mexp (<=64) keys; uniform trips
            const unsigned* L = binbuf + warp * BINBUF;
            for (int base = 0; base < mexp; base += 32) {
                int idx = base + lane;
                unsigned e = (idx < mexp) ? L[idx] : 0xFFFFFFFFu;
                int cl = 0, ce = 0;
                for (int t = 0; t < mexp; ++t) {
                    unsigned o = L[t];              // broadcast read
                    cl += (o < e);
                    ce += (o == e && t < idx);
                }
                if (idx < mexp && cl + ce == krem) s_keyout[warp] = e;
            }
        } else {
            // exact fallback: 32-step key bisection over the full global row
            const int kglob = s_k[warp];
            unsigned prefix = 0u;
            for (int bit = 31; bit >= 0; --bit) {
                unsigned cand2 = prefix | (1u << bit);
                unsigned cc = 0;
                for (int i2 = lane; i2 < T_DIM; i2 += 32)
                    if (i2 < n) cc += (f2k(xrow[i2]) < cand2) ? 1u : 0u;
#pragma unroll
                for (int o = 16; o; o >>= 1) cc += __shfl_down_sync(FULL, cc, o);
                cc = __shfl_sync(FULL, cc, 0);
                if (cc <= (unsigned)kglob) prefix = cand2;
            }
            if (lane == 0) s_keyout[warp] = prefix;
        }
    }
    __syncthreads();

    // ---- quantile interpolation + writeback ----
    if (tid < 3) {
        float vlo = k2f(s_keyout[2 * tid]);
        float vhi = k2f(s_keyout[2 * tid + 1]);
        out[b * (5 * C_DIM) + (2 + tid) * C_DIM + c] = vlo + s_w[tid] * (vhi - vlo);
    }
}

extern "C" void kernel_launch(void* const* d_in, const int* in_sizes, int n_in,
                              void* d_out, int out_size) {
    const float* x;
    const int* lengths;
    if (in_sizes[0] == B_DIM) {
        lengths = (const int*)d_in[0];
        x = (const float*)d_in[1];
    } else {
        x = (const float*)d_in[0];
        lengths = (const int*)d_in[1];
    }
    float* out = (float*)d_out;

    // 16 KB hist + 4 KB list = 20 KB dynamic -> 8 CTAs/SM
    size_t smem = (size_t)(NBIN + CAP) * sizeof(unsigned);
    cudaFuncSetAttribute(statpool_kernel,
                         cudaFuncAttributeMaxDynamicSharedMemorySize, (int)smem);
    statpool_kernel<<<B_DIM * C_DIM, NTHREADS, smem>>>(x, lengths, out);
}